// round 3
// baseline (speedup 1.0000x reference)
#include <cuda_runtime.h>
#include <cuda_fp16.h>

#define N_PTS 500000

// ---------------- scratch (device globals; no allocation allowed) ----------
__device__ float  g_wT[64 * 9 * 64];              // weights as [c][k][o]
__device__ float  g_y[3 * 64 * 128 * 128];        // conv outputs (pre-BN)
__device__ float  g_scale[3 * 64];
__device__ float  g_shift[3 * 64];
__device__ __align__(256) __half g_F[3 * 128 * 128 * 64];  // final planes [pl][h][w][c] fp16

// ---------------- kernel 0: transpose weights to [c*9+k][o] ----------------
__global__ void wT_kernel(const float* __restrict__ cw) {
    int idx = blockIdx.x * 256 + threadIdx.x;
    if (idx < 64 * 576) {
        int o = idx / 576;
        int r = idx % 576;           // r = c*9 + k
        g_wT[r * 64 + o] = cw[idx];
    }
}

// ---------------- kernel 1: conv3x3 stride2 pad1 (+bias) -------------------
// grid (128 h, 3 planes), block 256. Each block: one output row, all 64 o.
// thread: w = tid&127, o-group = tid>>7 (32 accumulators).
__global__ __launch_bounds__(256) void conv_kernel(
    const float* __restrict__ p0, const float* __restrict__ p1,
    const float* __restrict__ p2, const float* __restrict__ bias) {
    const float* p = blockIdx.y == 0 ? p0 : (blockIdx.y == 1 ? p1 : p2);
    int h   = blockIdx.x;
    int tid = threadIdx.x;
    int w   = tid & 127;
    int ob  = (tid >> 7) << 5;       // 0 or 32

    __shared__ float sE[8][3][128];  // even cols: sE[c][kh][w] = col 2w
    __shared__ float sO[8][3][129];  // odd cols:  sO[c][kh][j] = col 2j-1
    __shared__ float sW[8 * 9 * 64]; // [c][k][o]

    float acc[32];
#pragma unroll
    for (int i = 0; i < 32; i++) acc[i] = 0.f;

    int h2 = h * 2;
    for (int cc = 0; cc < 64; cc += 8) {
        __syncthreads();
        // stage input: cols -1..255 (257 values) for 3 rows x 8 channels
        for (int idx = tid; idx < 8 * 3 * 257; idx += 256) {
            int col = idx % 257 - 1;
            int t   = idx / 257;
            int kh  = t % 3;
            int c   = t / 3;
            int r   = h2 - 1 + kh;
            float v = 0.f;
            if ((unsigned)r < 256u && (unsigned)col < 256u)
                v = p[((cc + c) * 65536) + (r << 8) + col];
            if (col & 1) sO[c][kh][(col + 1) >> 1] = v;
            else         sE[c][kh][col >> 1] = v;
        }
        // stage weights (contiguous chunk, float4 copies)
        {
            const float4* wsrc = (const float4*)(g_wT + cc * 576);
            float4* wdst = (float4*)sW;
            for (int idx = tid; idx < (8 * 576) / 4; idx += 256) wdst[idx] = wsrc[idx];
        }
        __syncthreads();

        for (int c = 0; c < 8; c++) {
#pragma unroll
            for (int kh = 0; kh < 3; kh++) {
                float v0 = sO[c][kh][w];      // kw=0 -> col 2w-1
                float v1 = sE[c][kh][w];      // kw=1 -> col 2w
                float v2 = sO[c][kh][w + 1];  // kw=2 -> col 2w+1
                const float* wr = sW + (c * 9 + kh * 3) * 64 + ob;
#pragma unroll
                for (int oo = 0; oo < 32; oo++) {
                    float a = acc[oo];
                    a = fmaf(v0, wr[oo], a);
                    a = fmaf(v1, wr[64 + oo], a);
                    a = fmaf(v2, wr[128 + oo], a);
                    acc[oo] = a;
                }
            }
        }
    }
    int pl = blockIdx.y;
#pragma unroll
    for (int oo = 0; oo < 32; oo++) {
        int o = ob + oo;
        g_y[((pl * 64 + o) << 14) + (h << 7) + w] = acc[oo] + bias[o];
    }
}

// ---------------- kernel 2: BN statistics (fp64 accumulation) --------------
__global__ void stats_kernel(const float* __restrict__ gamma,
                             const float* __restrict__ beta) {
    int ch = blockIdx.x;              // pl*64 + o, 0..191
    const float* y = g_y + (ch << 14);
    double s = 0.0, q = 0.0;
    for (int i = threadIdx.x; i < 16384; i += 256) {
        double v = (double)y[i];
        s += v;
        q += v * v;
    }
    __shared__ double ss[256], sq[256];
    ss[threadIdx.x] = s;
    sq[threadIdx.x] = q;
    __syncthreads();
    for (int st = 128; st > 0; st >>= 1) {
        if (threadIdx.x < st) {
            ss[threadIdx.x] += ss[threadIdx.x + st];
            sq[threadIdx.x] += sq[threadIdx.x + st];
        }
        __syncthreads();
    }
    if (threadIdx.x == 0) {
        double mu  = ss[0] / 16384.0;
        double var = sq[0] / 16384.0 - mu * mu;
        float sc = (float)((double)gamma[ch & 63] / sqrt(var + 1e-5));
        g_scale[ch] = sc;
        g_shift[ch] = beta[ch & 63] - (float)mu * sc;
    }
}

// ---------------- kernel 3: BN+relu + avgpool, store fp16 [h][w][c] --------
__device__ __forceinline__ float fin_val(const float* __restrict__ p,
                                         int pl, int c, int i, int j) {
    float yv = g_y[((pl * 64 + c) << 14) + (i << 7) + j];
    float f  = fmaxf(fmaf(yv, g_scale[pl * 64 + c], g_shift[pl * 64 + c]), 0.f);
    const float* pc = p + (c << 16);
    float s = 0.f;
#pragma unroll
    for (int dh = 0; dh < 3; dh++) {
        int r = 2 * i - 1 + dh;
        if ((unsigned)r < 256u) {
            const float* pr = pc + (r << 8);
#pragma unroll
            for (int dw = 0; dw < 3; dw++) {
                int col = 2 * j - 1 + dw;
                if ((unsigned)col < 256u) s += pr[col];
            }
        }
    }
    return f + s * (1.f / 9.f);
}

__global__ __launch_bounds__(256) void finalize_kernel(
    const float* __restrict__ p0, const float* __restrict__ p1,
    const float* __restrict__ p2) {
    int pl = blockIdx.y, i = blockIdx.x;
    const float* p = pl == 0 ? p0 : (pl == 1 ? p1 : p2);
    int tid = threadIdx.x;
    int j  = tid >> 1;
    int cg = (tid & 1) << 5;   // 0 or 32: 32 channels per thread

    uint4* dst = (uint4*)(g_F + ((((pl << 7) + i) << 7) + j) * 64 + cg);
#pragma unroll
    for (int qq = 0; qq < 4; qq++) {
        unsigned int u[4];
#pragma unroll
        for (int m = 0; m < 4; m++) {
            int c0 = cg + qq * 8 + m * 2;
            float f0 = fin_val(p, pl, c0, i, j);
            float f1 = fin_val(p, pl, c0 + 1, i, j);
            __half2 h2 = __floats2half2_rn(f0, f1);
            u[m] = *reinterpret_cast<unsigned int*>(&h2);
        }
        dst[qq] = make_uint4(u[0], u[1], u[2], u[3]);
    }
}

// ---------------- kernel 4: bicubic triplane sampling ----------------------
__device__ __forceinline__ void cubw(float t, float w[4]) {
    const float A_ = -0.75f;
    float t1 = t + 1.f;
    w[0] = ((A_ * t1 - 5.f * A_) * t1 + 8.f * A_) * t1 - 4.f * A_;
    w[1] = ((A_ + 2.f) * t - (A_ + 3.f)) * t * t + 1.f;
    float s = 1.f - t;
    w[2] = ((A_ + 2.f) * s - (A_ + 3.f)) * s * s + 1.f;
    w[3] = 1.f - w[0] - w[1] - w[2];
}

__global__ __launch_bounds__(256) void sample_kernel(
    const float* __restrict__ coords, const float* __restrict__ noise,
    float* __restrict__ out) {
    int gw = (blockIdx.x * blockDim.x + threadIdx.x) >> 5;  // one warp per point
    if (gw >= N_PTS) return;
    int lane = threadIdx.x & 31;

    float c0 = (coords[gw * 3 + 0] + 1.f) * 0.5f;
    float c1 = (coords[gw * 3 + 1] + 1.f) * 0.5f;
    float c2 = (coords[gw * 3 + 2] + 1.f) * 0.5f;

    float accx = 0.f, accy = 0.f;
#pragma unroll
    for (int pl = 0; pl < 3; pl++) {
        const float* nz = noise + pl * (N_PTS * 2) + gw * 2;
        float g0, g1;
        if (pl == 0)      { g0 = c0; g1 = c1; }
        else if (pl == 1) { g0 = c1; g1 = c2; }
        else              { g0 = c0; g1 = c2; }
        g0 += nz[0];
        g1 += nz[1];
        float gx = fminf(fmaxf((g0 + 1.f) * 63.5f, 0.f), 127.f);
        float gy = fminf(fmaxf((g1 + 1.f) * 63.5f, 0.f), 127.f);
        float xf = floorf(gx), yf = floorf(gy);
        float tx = gx - xf, ty = gy - yf;
        int x0 = (int)xf, y0 = (int)yf;
        float wx[4], wy[4];
        cubw(tx, wx);
        cubw(ty, wy);
        const __half* base = g_F + (pl << 20) + (lane << 1);
#pragma unroll
        for (int ii = 0; ii < 4; ii++) {
            int yi = min(max(y0 + ii - 1, 0), 127);
            const __half* row = base + (yi << 13);   // yi*128*64
            float wyi = wy[ii];
#pragma unroll
            for (int jj = 0; jj < 4; jj++) {
                int xi = min(max(x0 + jj - 1, 0), 127);
                __half2 hv = *(const __half2*)(row + (xi << 6));
                float2 v = __half22float2(hv);
                float ww = wyi * wx[jj];
                accx = fmaf(ww, v.x, accx);
                accy = fmaf(ww, v.y, accy);
            }
        }
    }
    float2* po = (float2*)(out + gw * 64);
    po[lane] = make_float2(accx, accy);
}

// ---------------- launcher -------------------------------------------------
extern "C" void kernel_launch(void* const* d_in, const int* in_sizes, int n_in,
                              void* d_out, int out_size) {
    const float* coords = (const float*)d_in[0];
    const float* noise  = (const float*)d_in[1];
    const float* px     = (const float*)d_in[2];
    const float* py     = (const float*)d_in[3];
    const float* pz     = (const float*)d_in[4];
    const float* cw     = (const float*)d_in[5];
    const float* cb     = (const float*)d_in[6];
    const float* gm     = (const float*)d_in[7];
    const float* bt     = (const float*)d_in[8];
    float* out = (float*)d_out;

    wT_kernel<<<144, 256>>>(cw);
    conv_kernel<<<dim3(128, 3), 256>>>(px, py, pz, cb);
    stats_kernel<<<192, 256>>>(gm, bt);
    finalize_kernel<<<dim3(128, 3), 256>>>(px, py, pz);
    sample_kernel<<<(N_PTS * 32) / 256, 256>>>(coords, noise, out);
}

// round 4
// speedup vs baseline: 1.0029x; 1.0029x over previous
#include <cuda_runtime.h>
#include <cuda_fp16.h>

#define N_PTS 500000

// ---------------- scratch (device globals; no allocation allowed) ----------
__device__ float  g_wT[64 * 9 * 64];              // weights as [c][k][o]
__device__ float  g_y[3 * 64 * 128 * 128];        // conv outputs (pre-BN)
__device__ float  g_scale[3 * 64];
__device__ float  g_shift[3 * 64];
__device__ __align__(256) __half g_F[3 * 128 * 128 * 64];  // final planes [pl][h][w][c] fp16

// ---------------- kernel 0: transpose weights to [c*9+k][o] ----------------
__global__ void wT_kernel(const float* __restrict__ cw) {
    int idx = blockIdx.x * 256 + threadIdx.x;
    if (idx < 64 * 576) {
        int o = idx / 576;
        int r = idx % 576;           // r = c*9 + k
        g_wT[r * 64 + o] = cw[idx];
    }
}

// ---------------- kernel 1: conv3x3 stride2 pad1 (+bias) -------------------
// grid (128 h, 3 planes), block 256. Each block: one output row, all 64 o.
// thread: w = tid&127, o-group = tid>>7 (32 accumulators).
__global__ __launch_bounds__(256) void conv_kernel(
    const float* __restrict__ p0, const float* __restrict__ p1,
    const float* __restrict__ p2, const float* __restrict__ bias) {
    const float* p = blockIdx.y == 0 ? p0 : (blockIdx.y == 1 ? p1 : p2);
    int h   = blockIdx.x;
    int tid = threadIdx.x;
    int w   = tid & 127;
    int ob  = (tid >> 7) << 5;       // 0 or 32

    __shared__ float sE[8][3][128];  // even cols: sE[c][kh][w] = col 2w
    __shared__ float sO[8][3][129];  // odd cols:  sO[c][kh][j] = col 2j-1
    __shared__ float sW[8 * 9 * 64]; // [c][k][o]

    float acc[32];
#pragma unroll
    for (int i = 0; i < 32; i++) acc[i] = 0.f;

    int h2 = h * 2;
    for (int cc = 0; cc < 64; cc += 8) {
        __syncthreads();
        // stage input: cols -1..255 (257 values) for 3 rows x 8 channels
        for (int idx = tid; idx < 8 * 3 * 257; idx += 256) {
            int col = idx % 257 - 1;
            int t   = idx / 257;
            int kh  = t % 3;
            int c   = t / 3;
            int r   = h2 - 1 + kh;
            float v = 0.f;
            if ((unsigned)r < 256u && (unsigned)col < 256u)
                v = p[((cc + c) * 65536) + (r << 8) + col];
            if (col & 1) sO[c][kh][(col + 1) >> 1] = v;
            else         sE[c][kh][col >> 1] = v;
        }
        // stage weights (contiguous chunk, float4 copies)
        {
            const float4* wsrc = (const float4*)(g_wT + cc * 576);
            float4* wdst = (float4*)sW;
            for (int idx = tid; idx < (8 * 576) / 4; idx += 256) wdst[idx] = wsrc[idx];
        }
        __syncthreads();

        for (int c = 0; c < 8; c++) {
#pragma unroll
            for (int kh = 0; kh < 3; kh++) {
                float v0 = sO[c][kh][w];      // kw=0 -> col 2w-1
                float v1 = sE[c][kh][w];      // kw=1 -> col 2w
                float v2 = sO[c][kh][w + 1];  // kw=2 -> col 2w+1
                const float* wr = sW + (c * 9 + kh * 3) * 64 + ob;
#pragma unroll
                for (int oo = 0; oo < 32; oo++) {
                    float a = acc[oo];
                    a = fmaf(v0, wr[oo], a);
                    a = fmaf(v1, wr[64 + oo], a);
                    a = fmaf(v2, wr[128 + oo], a);
                    acc[oo] = a;
                }
            }
        }
    }
    int pl = blockIdx.y;
#pragma unroll
    for (int oo = 0; oo < 32; oo++) {
        int o = ob + oo;
        g_y[((pl * 64 + o) << 14) + (h << 7) + w] = acc[oo] + bias[o];
    }
}

// ---------------- kernel 2: BN statistics (fp64 accumulation) --------------
__global__ void stats_kernel(const float* __restrict__ gamma,
                             const float* __restrict__ beta) {
    int ch = blockIdx.x;              // pl*64 + o, 0..191
    const float* y = g_y + (ch << 14);
    double s = 0.0, q = 0.0;
    for (int i = threadIdx.x; i < 16384; i += 256) {
        double v = (double)y[i];
        s += v;
        q += v * v;
    }
    __shared__ double ss[256], sq[256];
    ss[threadIdx.x] = s;
    sq[threadIdx.x] = q;
    __syncthreads();
    for (int st = 128; st > 0; st >>= 1) {
        if (threadIdx.x < st) {
            ss[threadIdx.x] += ss[threadIdx.x + st];
            sq[threadIdx.x] += sq[threadIdx.x + st];
        }
        __syncthreads();
    }
    if (threadIdx.x == 0) {
        double mu  = ss[0] / 16384.0;
        double var = sq[0] / 16384.0 - mu * mu;
        float sc = (float)((double)gamma[ch & 63] / sqrt(var + 1e-5));
        g_scale[ch] = sc;
        g_shift[ch] = beta[ch & 63] - (float)mu * sc;
    }
}

// ---------------- kernel 3: BN+relu + avgpool, store fp16 [h][w][c] --------
__device__ __forceinline__ float fin_val(const float* __restrict__ p,
                                         int pl, int c, int i, int j) {
    float yv = g_y[((pl * 64 + c) << 14) + (i << 7) + j];
    float f  = fmaxf(fmaf(yv, g_scale[pl * 64 + c], g_shift[pl * 64 + c]), 0.f);
    const float* pc = p + (c << 16);
    float s = 0.f;
#pragma unroll
    for (int dh = 0; dh < 3; dh++) {
        int r = 2 * i - 1 + dh;
        if ((unsigned)r < 256u) {
            const float* pr = pc + (r << 8);
#pragma unroll
            for (int dw = 0; dw < 3; dw++) {
                int col = 2 * j - 1 + dw;
                if ((unsigned)col < 256u) s += pr[col];
            }
        }
    }
    return f + s * (1.f / 9.f);
}

__global__ __launch_bounds__(256) void finalize_kernel(
    const float* __restrict__ p0, const float* __restrict__ p1,
    const float* __restrict__ p2) {
    int pl = blockIdx.y, i = blockIdx.x;
    const float* p = pl == 0 ? p0 : (pl == 1 ? p1 : p2);
    int tid = threadIdx.x;
    int j  = tid >> 1;
    int cg = (tid & 1) << 5;   // 0 or 32: 32 channels per thread

    uint4* dst = (uint4*)(g_F + ((((pl << 7) + i) << 7) + j) * 64 + cg);
#pragma unroll
    for (int qq = 0; qq < 4; qq++) {
        unsigned int u[4];
#pragma unroll
        for (int m = 0; m < 4; m++) {
            int c0 = cg + qq * 8 + m * 2;
            float f0 = fin_val(p, pl, c0, i, j);
            float f1 = fin_val(p, pl, c0 + 1, i, j);
            __half2 h2 = __floats2half2_rn(f0, f1);
            u[m] = *reinterpret_cast<unsigned int*>(&h2);
        }
        dst[qq] = make_uint4(u[0], u[1], u[2], u[3]);
    }
}

// ---------------- kernel 4: bicubic triplane sampling ----------------------
__device__ __forceinline__ void cubw(float t, float w[4]) {
    const float A_ = -0.75f;
    float t1 = t + 1.f;
    w[0] = ((A_ * t1 - 5.f * A_) * t1 + 8.f * A_) * t1 - 4.f * A_;
    w[1] = ((A_ + 2.f) * t - (A_ + 3.f)) * t * t + 1.f;
    float s = 1.f - t;
    w[2] = ((A_ + 2.f) * s - (A_ + 3.f)) * s * s + 1.f;
    w[3] = 1.f - w[0] - w[1] - w[2];
}

__global__ __launch_bounds__(256) void sample_kernel(
    const float* __restrict__ coords, const float* __restrict__ noise,
    float* __restrict__ out) {
    int gw = (blockIdx.x * blockDim.x + threadIdx.x) >> 5;  // one warp per point
    if (gw >= N_PTS) return;
    int lane = threadIdx.x & 31;

    float c0 = (coords[gw * 3 + 0] + 1.f) * 0.5f;
    float c1 = (coords[gw * 3 + 1] + 1.f) * 0.5f;
    float c2 = (coords[gw * 3 + 2] + 1.f) * 0.5f;

    float accx = 0.f, accy = 0.f;
#pragma unroll
    for (int pl = 0; pl < 3; pl++) {
        const float* nz = noise + pl * (N_PTS * 2) + gw * 2;
        float g0, g1;
        if (pl == 0)      { g0 = c0; g1 = c1; }
        else if (pl == 1) { g0 = c1; g1 = c2; }
        else              { g0 = c0; g1 = c2; }
        g0 += nz[0];
        g1 += nz[1];
        float gx = fminf(fmaxf((g0 + 1.f) * 63.5f, 0.f), 127.f);
        float gy = fminf(fmaxf((g1 + 1.f) * 63.5f, 0.f), 127.f);
        float xf = floorf(gx), yf = floorf(gy);
        float tx = gx - xf, ty = gy - yf;
        int x0 = (int)xf, y0 = (int)yf;
        float wx[4], wy[4];
        cubw(tx, wx);
        cubw(ty, wy);
        const __half* base = g_F + (pl << 20) + (lane << 1);
#pragma unroll
        for (int ii = 0; ii < 4; ii++) {
            int yi = min(max(y0 + ii - 1, 0), 127);
            const __half* row = base + (yi << 13);   // yi*128*64
            float wyi = wy[ii];
#pragma unroll
            for (int jj = 0; jj < 4; jj++) {
                int xi = min(max(x0 + jj - 1, 0), 127);
                __half2 hv = *(const __half2*)(row + (xi << 6));
                float2 v = __half22float2(hv);
                float ww = wyi * wx[jj];
                accx = fmaf(ww, v.x, accx);
                accy = fmaf(ww, v.y, accy);
            }
        }
    }
    float2* po = (float2*)(out + gw * 64);
    po[lane] = make_float2(accx, accy);
}

// ---------------- launcher -------------------------------------------------
extern "C" void kernel_launch(void* const* d_in, const int* in_sizes, int n_in,
                              void* d_out, int out_size) {
    const float* coords = (const float*)d_in[0];
    const float* noise  = (const float*)d_in[1];
    const float* px     = (const float*)d_in[2];
    const float* py     = (const float*)d_in[3];
    const float* pz     = (const float*)d_in[4];
    const float* cw     = (const float*)d_in[5];
    const float* cb     = (const float*)d_in[6];
    const float* gm     = (const float*)d_in[7];
    const float* bt     = (const float*)d_in[8];
    float* out = (float*)d_out;

    wT_kernel<<<144, 256>>>(cw);
    conv_kernel<<<dim3(128, 3), 256>>>(px, py, pz, cb);
    stats_kernel<<<192, 256>>>(gm, bt);
    finalize_kernel<<<dim3(128, 3), 256>>>(px, py, pz);
    sample_kernel<<<(N_PTS * 32) / 256, 256>>>(coords, noise, out);
}